// round 3
// baseline (speedup 1.0000x reference)
#include <cuda_runtime.h>
#include <cuda_bf16.h>
#include <cstddef>

// Problem dims (fixed by the dataset)
#define BB 4
#define CC 512
#define NN 4096   // H*W = 64*64

// ---------------------------------------------------------------------------
// Scratch (allocation-free rule -> __device__ globals)
// ---------------------------------------------------------------------------
__device__ float g_xhat_c[(size_t)BB * CC * NN];   // normalized f_c
__device__ float g_xhat_s[(size_t)BB * CC * NN];   // normalized f_s
__device__ float g_f[(size_t)BB * CC * NN];        // queries  [B,C,N]
__device__ float g_g[(size_t)BB * CC * NN];        // keys     [B,C,N]
__device__ float g_h[(size_t)BB * CC * NN];        // values   [B,C,N]
__device__ float g_att[(size_t)BB * NN * NN];      // scores / attention [B,N,N]
__device__ float g_out2[(size_t)BB * CC * NN];     // attention output [B,C,N]

// ---------------------------------------------------------------------------
// Channel norm: one block per (b,c) row of 4096 spatial elements.
// var uses ddof=1 (unbiased), eps=1e-5, matching the reference.
// ---------------------------------------------------------------------------
__global__ void __launch_bounds__(256) norm_kernel(const float* __restrict__ x,
                                                   float* __restrict__ y)
{
    const size_t base = (size_t)blockIdx.x * NN;
    const float* row = x + base;
    float* out = y + base;

    float s = 0.f, s2 = 0.f;
    #pragma unroll 4
    for (int i = threadIdx.x; i < NN; i += 256) {
        float v = row[i];
        s += v; s2 += v * v;
    }
    __shared__ float red[64];
    #pragma unroll
    for (int o = 16; o; o >>= 1) {
        s  += __shfl_xor_sync(0xffffffffu, s,  o);
        s2 += __shfl_xor_sync(0xffffffffu, s2, o);
    }
    int w = threadIdx.x >> 5, l = threadIdx.x & 31;
    if (l == 0) { red[w] = s; red[32 + w] = s2; }
    __syncthreads();
    float ts = 0.f, ts2 = 0.f;
    #pragma unroll
    for (int i = 0; i < 8; i++) { ts += red[i]; ts2 += red[32 + i]; }
    float mean = ts * (1.0f / NN);
    float var = (ts2 - (float)NN * mean * mean) * (1.0f / (NN - 1));
    float inv = rsqrtf(var + 1e-5f);

    #pragma unroll 4
    for (int i = threadIdx.x; i < NN; i += 256)
        out[i] = (row[i] - mean) * inv;
}

// ---------------------------------------------------------------------------
// Generic batched SGEMM: Y[z] = A[z] * B[z] (+ bias) (+ resid)
//   128x128 tile, BK=8, 256 threads, 8x8 micro-tile per thread.
//   AT: A source stored K-major, i.e. A[k][m] with row length M  (used for f^T)
//   BT: B source stored N-major, i.e. B[n][k] with row length K  (used for att^T)
// All dims are multiples of 128 / 8 for this problem; no bounds checks needed.
// ---------------------------------------------------------------------------
template <bool AT, bool BT>
__global__ void __launch_bounds__(256)
gemm_kernel(const float* __restrict__ A, const float* __restrict__ Bm,
            const float* __restrict__ bias, const float* __restrict__ resid,
            float* __restrict__ Y,
            int M, int N, int K,
            size_t sA, size_t sB, size_t sY)
{
    A  += (size_t)blockIdx.z * sA;
    Bm += (size_t)blockIdx.z * sB;
    Y  += (size_t)blockIdx.z * sY;
    const float* R = resid ? resid + (size_t)blockIdx.z * sY : nullptr;

    __shared__ float As[8][128];
    __shared__ float Bs[8][128];

    const int tid = threadIdx.x;
    const int tx = tid & 15;        // column group (8 cols)
    const int ty = tid >> 4;        // row group (8 rows)
    const int mBase = blockIdx.y * 128;
    const int nBase = blockIdx.x * 128;

    float acc[8][8];
    #pragma unroll
    for (int i = 0; i < 8; i++)
        #pragma unroll
        for (int j = 0; j < 8; j++) acc[i][j] = 0.f;

    for (int k0 = 0; k0 < K; k0 += 8) {
        // ---- load A tile ----
        if constexpr (!AT) {
            int row = tid >> 1, kq = (tid & 1) * 4;
            float4 v = *(const float4*)&A[(size_t)(mBase + row) * K + k0 + kq];
            As[kq + 0][row] = v.x; As[kq + 1][row] = v.y;
            As[kq + 2][row] = v.z; As[kq + 3][row] = v.w;
        } else {
            int k = tid >> 5, c4 = (tid & 31) * 4;
            float4 v = *(const float4*)&A[(size_t)(k0 + k) * M + mBase + c4];
            *(float4*)&As[k][c4] = v;
        }
        // ---- load B tile ----
        if constexpr (!BT) {
            int k = tid >> 5, c4 = (tid & 31) * 4;
            float4 v = *(const float4*)&Bm[(size_t)(k0 + k) * N + nBase + c4];
            *(float4*)&Bs[k][c4] = v;
        } else {
            int n = tid >> 1, kq = (tid & 1) * 4;
            float4 v = *(const float4*)&Bm[(size_t)(nBase + n) * K + k0 + kq];
            Bs[kq + 0][n] = v.x; Bs[kq + 1][n] = v.y;
            Bs[kq + 2][n] = v.z; Bs[kq + 3][n] = v.w;
        }
        __syncthreads();

        #pragma unroll
        for (int kk = 0; kk < 8; kk++) {
            float a[8], b[8];
            *(float4*)(a)     = *(const float4*)&As[kk][ty * 8];
            *(float4*)(a + 4) = *(const float4*)&As[kk][ty * 8 + 4];
            *(float4*)(b)     = *(const float4*)&Bs[kk][tx * 8];
            *(float4*)(b + 4) = *(const float4*)&Bs[kk][tx * 8 + 4];
            #pragma unroll
            for (int i = 0; i < 8; i++)
                #pragma unroll
                for (int j = 0; j < 8; j++)
                    acc[i][j] += a[i] * b[j];
        }
        __syncthreads();
    }

    // ---- epilogue ----
    #pragma unroll
    for (int i = 0; i < 8; i++) {
        int m = mBase + ty * 8 + i;
        float bv = bias ? bias[m] : 0.f;
        #pragma unroll
        for (int j = 0; j < 8; j += 4) {
            size_t off = (size_t)m * N + nBase + tx * 8 + j;
            float4 r;
            r.x = acc[i][j + 0] + bv;
            r.y = acc[i][j + 1] + bv;
            r.z = acc[i][j + 2] + bv;
            r.w = acc[i][j + 3] + bv;
            if (R) {
                float4 rv = *(const float4*)&R[off];
                r.x += rv.x; r.y += rv.y; r.z += rv.z; r.w += rv.w;
            }
            *(float4*)&Y[off] = r;
        }
    }
}

// ---------------------------------------------------------------------------
// Row softmax over 4096 elements, in place. One block (256 thr) per row;
// 16 values per thread kept in registers -> single read + single write.
// ---------------------------------------------------------------------------
__global__ void __launch_bounds__(256) softmax_kernel(float* __restrict__ S)
{
    float* row = S + (size_t)blockIdx.x * NN;
    float v[16];
    float mx = -1e30f;
    #pragma unroll
    for (int j = 0; j < 16; j++) {
        v[j] = row[threadIdx.x + j * 256];
        mx = fmaxf(mx, v[j]);
    }
    __shared__ float red[8];
    #pragma unroll
    for (int o = 16; o; o >>= 1) mx = fmaxf(mx, __shfl_xor_sync(0xffffffffu, mx, o));
    if ((threadIdx.x & 31) == 0) red[threadIdx.x >> 5] = mx;
    __syncthreads();
    mx = red[0];
    #pragma unroll
    for (int i = 1; i < 8; i++) mx = fmaxf(mx, red[i]);
    __syncthreads();

    float sum = 0.f;
    #pragma unroll
    for (int j = 0; j < 16; j++) {
        v[j] = expf(v[j] - mx);
        sum += v[j];
    }
    #pragma unroll
    for (int o = 16; o; o >>= 1) sum += __shfl_xor_sync(0xffffffffu, sum, o);
    if ((threadIdx.x & 31) == 0) red[threadIdx.x >> 5] = sum;
    __syncthreads();
    sum = 0.f;
    #pragma unroll
    for (int i = 0; i < 8; i++) sum += red[i];
    float inv = 1.0f / sum;

    #pragma unroll
    for (int j = 0; j < 16; j++)
        row[threadIdx.x + j * 256] = v[j] * inv;
}

// ---------------------------------------------------------------------------
// Launch
// ---------------------------------------------------------------------------
extern "C" void kernel_launch(void* const* d_in, const int* in_sizes, int n_in,
                              void* d_out, int out_size)
{
    (void)in_sizes; (void)n_in; (void)out_size;
    const float* f_c   = (const float*)d_in[0];
    const float* f_s   = (const float*)d_in[1];
    const float* W_c1  = (const float*)d_in[2];
    const float* b_c1  = (const float*)d_in[3];
    const float* W_s1  = (const float*)d_in[4];
    const float* b_s1  = (const float*)d_in[5];
    const float* W_s2  = (const float*)d_in[6];
    const float* b_s2  = (const float*)d_in[7];
    const float* W_csc = (const float*)d_in[8];
    const float* b_csc = (const float*)d_in[9];
    float* out = (float*)d_out;

    float *xc, *xs, *pf, *pg, *ph, *att, *o2;
    cudaGetSymbolAddress((void**)&xc,  g_xhat_c);
    cudaGetSymbolAddress((void**)&xs,  g_xhat_s);
    cudaGetSymbolAddress((void**)&pf,  g_f);
    cudaGetSymbolAddress((void**)&pg,  g_g);
    cudaGetSymbolAddress((void**)&ph,  g_h);
    cudaGetSymbolAddress((void**)&att, g_att);
    cudaGetSymbolAddress((void**)&o2,  g_out2);

    const size_t sCN = (size_t)CC * NN;        // per-batch stride of [C,N] tensors
    const size_t sNN = (size_t)NN * NN;        // per-batch stride of [N,N] tensors

    // 1) channel norm
    norm_kernel<<<BB * CC, 256>>>(f_c, xc);
    norm_kernel<<<BB * CC, 256>>>(f_s, xs);

    // 2) 1x1 convs: f = W_c1 @ xc + b ; g = W_s1 @ xs + b ; h = W_s2 @ xs + b
    {
        dim3 grid(NN / 128, CC / 128, BB);   // (32,4,4)
        gemm_kernel<false, false><<<grid, 256>>>(W_c1, xc, b_c1, nullptr, pf,
                                                 CC, NN, CC, 0, sCN, sCN);
        gemm_kernel<false, false><<<grid, 256>>>(W_s1, xs, b_s1, nullptr, pg,
                                                 CC, NN, CC, 0, sCN, sCN);
        gemm_kernel<false, false><<<grid, 256>>>(W_s2, xs, b_s2, nullptr, ph,
                                                 CC, NN, CC, 0, sCN, sCN);
    }

    // 3) scores = f^T @ g   [B, N, N]
    {
        dim3 grid(NN / 128, NN / 128, BB);   // (32,32,4)
        gemm_kernel<true, false><<<grid, 256>>>(pf, pg, nullptr, nullptr, att,
                                                NN, NN, CC, sCN, sCN, sNN);
    }

    // 4) row softmax
    softmax_kernel<<<BB * NN, 256>>>(att);

    // 5) out2 = h @ att^T   [B, C, N]
    {
        dim3 grid(NN / 128, CC / 128, BB);
        gemm_kernel<false, true><<<grid, 256>>>(ph, att, nullptr, nullptr, o2,
                                                CC, NN, NN, sCN, sNN, sCN);
    }

    // 6) result = W_csc @ out2 + b_csc + f_c
    {
        dim3 grid(NN / 128, CC / 128, BB);
        gemm_kernel<false, false><<<grid, 256>>>(W_csc, o2, b_csc, f_c, out,
                                                 CC, NN, CC, 0, sCN, sCN);
    }
}

// round 6
// speedup vs baseline: 2.3938x; 2.3938x over previous
#include <cuda_runtime.h>
#include <cuda_bf16.h>
#include <cstdint>
#include <cstddef>

#define BB 4
#define CC 512
#define NN 4096

// ---------------------------------------------------------------------------
// Scratch (allocation-free rule -> __device__ globals)
// ---------------------------------------------------------------------------
__device__ float g_stats[BB * CC * 2];
__device__ __nv_bfloat16 g_xcT_hi[(size_t)BB * NN * CC], g_xcT_lo[(size_t)BB * NN * CC];
__device__ __nv_bfloat16 g_xsT_hi[(size_t)BB * NN * CC], g_xsT_lo[(size_t)BB * NN * CC];
__device__ __nv_bfloat16 g_W_hi[4][CC * CC], g_W_lo[4][CC * CC];
__device__ __nv_bfloat16 g_qt_hi[(size_t)BB * NN * CC], g_qt_lo[(size_t)BB * NN * CC];
__device__ __nv_bfloat16 g_kt_hi[(size_t)BB * NN * CC], g_kt_lo[(size_t)BB * NN * CC];
__device__ __nv_bfloat16 g_h_hi[(size_t)BB * CC * NN],  g_h_lo[(size_t)BB * CC * NN];
__device__ __nv_bfloat16 g_o2t_hi[(size_t)BB * NN * CC], g_o2t_lo[(size_t)BB * NN * CC];
__device__ float g_scores[(size_t)BB * NN * NN];
__device__ __nv_bfloat16 g_att_hi[(size_t)BB * NN * NN], g_att_lo[(size_t)BB * NN * NN];

// ---------------------------------------------------------------------------
// helpers
// ---------------------------------------------------------------------------
__device__ __forceinline__ uint32_t smem_u32(const void* p) {
    uint32_t a;
    asm("{ .reg .u64 t; cvta.to.shared.u64 t, %1; cvt.u32.u64 %0, t; }" : "=r"(a) : "l"(p));
    return a;
}

__device__ __forceinline__ void ldm4(uint32_t* r, uint32_t addr) {
    asm volatile("ldmatrix.sync.aligned.m8n8.x4.shared.b16 {%0,%1,%2,%3}, [%4];"
        : "=r"(r[0]), "=r"(r[1]), "=r"(r[2]), "=r"(r[3]) : "r"(addr));
}

__device__ __forceinline__ void mma16816(float* d, const uint32_t* a, const uint32_t* b) {
    asm volatile("mma.sync.aligned.m16n8k16.row.col.f32.bf16.bf16.f32 "
        "{%0,%1,%2,%3}, {%4,%5,%6,%7}, {%8,%9}, {%0,%1,%2,%3};"
        : "+f"(d[0]), "+f"(d[1]), "+f"(d[2]), "+f"(d[3])
        : "r"(a[0]), "r"(a[1]), "r"(a[2]), "r"(a[3]), "r"(b[0]), "r"(b[1]));
}

// ---------------------------------------------------------------------------
// Norm stats: one block per (b,c) row (ddof=1, eps=1e-5)
// ---------------------------------------------------------------------------
__global__ void __launch_bounds__(256) stats_kernel(const float* __restrict__ x,
                                                    float* __restrict__ stats)
{
    const float* row = x + (size_t)blockIdx.x * NN;
    float s = 0.f, s2 = 0.f;
    #pragma unroll 4
    for (int i = threadIdx.x; i < NN; i += 256) { float v = row[i]; s += v; s2 += v * v; }
    __shared__ float red[64];
    #pragma unroll
    for (int o = 16; o; o >>= 1) {
        s  += __shfl_xor_sync(0xffffffffu, s,  o);
        s2 += __shfl_xor_sync(0xffffffffu, s2, o);
    }
    int w = threadIdx.x >> 5;
    if ((threadIdx.x & 31) == 0) { red[w] = s; red[32 + w] = s2; }
    __syncthreads();
    if (threadIdx.x == 0) {
        float ts = 0.f, ts2 = 0.f;
        #pragma unroll
        for (int i = 0; i < 8; i++) { ts += red[i]; ts2 += red[32 + i]; }
        float mean = ts * (1.0f / NN);
        float var = (ts2 - (float)NN * mean * mean) * (1.0f / (NN - 1));
        stats[blockIdx.x * 2]     = mean;
        stats[blockIdx.x * 2 + 1] = rsqrtf(var + 1e-5f);
    }
}

// ---------------------------------------------------------------------------
// Normalize + transpose ([B,C,N] -> [B,N,C]) + bf16 hi/lo split
// ---------------------------------------------------------------------------
__global__ void __launch_bounds__(256) norm_tsplit_kernel(
    const float* __restrict__ x, const float* __restrict__ stats,
    __nv_bfloat16* __restrict__ hiT, __nv_bfloat16* __restrict__ loT)
{
    __shared__ float tile[32][33];
    int b = blockIdx.z, c0 = blockIdx.y * 32, n0 = blockIdx.x * 32;
    int tx = threadIdx.x & 31, ty = threadIdx.x >> 5;
    #pragma unroll
    for (int p = 0; p < 4; p++) {
        int ci = p * 8 + ty;
        int si = (b * CC + c0 + ci) * 2;
        float mean = stats[si], inv = stats[si + 1];
        float v = x[((size_t)(b * CC + c0 + ci)) * NN + n0 + tx];
        tile[ci][tx] = (v - mean) * inv;
    }
    __syncthreads();
    #pragma unroll
    for (int p = 0; p < 4; p++) {
        int ni = p * 8 + ty;
        float v = tile[tx][ni];
        __nv_bfloat16 h = __float2bfloat16(v);
        __nv_bfloat16 l = __float2bfloat16(v - __bfloat162float(h));
        size_t o = ((size_t)b * NN + n0 + ni) * CC + c0 + tx;
        hiT[o] = h; loT[o] = l;
    }
}

__global__ void __launch_bounds__(256) split_kernel(const float* __restrict__ w,
                                                    __nv_bfloat16* __restrict__ hi,
                                                    __nv_bfloat16* __restrict__ lo, int n)
{
    int i = blockIdx.x * 256 + threadIdx.x;
    if (i < n) {
        float v = w[i];
        __nv_bfloat16 h = __float2bfloat16(v);
        hi[i] = h; lo[i] = __float2bfloat16(v - __bfloat162float(h));
    }
}

// ---------------------------------------------------------------------------
// Row softmax (4096) -> bf16 hi/lo attention
// ---------------------------------------------------------------------------
__global__ void __launch_bounds__(256) softmax_kernel(const float* __restrict__ S,
                                                      __nv_bfloat16* __restrict__ Ahi,
                                                      __nv_bfloat16* __restrict__ Alo)
{
    const float* row = S + (size_t)blockIdx.x * NN;
    float v[16];
    float mx = -1e30f;
    #pragma unroll
    for (int j = 0; j < 16; j++) { v[j] = row[threadIdx.x + j * 256]; mx = fmaxf(mx, v[j]); }
    __shared__ float red[8];
    #pragma unroll
    for (int o = 16; o; o >>= 1) mx = fmaxf(mx, __shfl_xor_sync(0xffffffffu, mx, o));
    if ((threadIdx.x & 31) == 0) red[threadIdx.x >> 5] = mx;
    __syncthreads();
    mx = red[0];
    #pragma unroll
    for (int i = 1; i < 8; i++) mx = fmaxf(mx, red[i]);
    __syncthreads();
    float sum = 0.f;
    #pragma unroll
    for (int j = 0; j < 16; j++) { v[j] = expf(v[j] - mx); sum += v[j]; }
    #pragma unroll
    for (int o = 16; o; o >>= 1) sum += __shfl_xor_sync(0xffffffffu, sum, o);
    if ((threadIdx.x & 31) == 0) red[threadIdx.x >> 5] = sum;
    __syncthreads();
    sum = 0.f;
    #pragma unroll
    for (int i = 0; i < 8; i++) sum += red[i];
    float inv = 1.0f / sum;
    size_t base = (size_t)blockIdx.x * NN + threadIdx.x;
    #pragma unroll
    for (int j = 0; j < 16; j++) {
        float p = v[j] * inv;
        __nv_bfloat16 h = __float2bfloat16(p);
        Ahi[base + j * 256] = h;
        Alo[base + j * 256] = __float2bfloat16(p - __bfloat162float(h));
    }
}

// ---------------------------------------------------------------------------
// HMMA split-bf16 GEMM:  D[M,N] = (Ahi+Alo)[M,K] . (Bhi+Blo)[N,K]^T
// 128x128 CTA tile, BK=32 bf16, cp.async double buffer, mma.sync m16n8k16.
// 8 warps: warp (wm = wid&1, wn = wid>>1) owns a 64(M) x 32(N) sub-tile.
// EPI: 0 = fp32 out             1 = fp32 out + bias[m] + resid
//      2 = bf16 hi/lo + bias[n] 3 = bf16 hi/lo + bias[m]  4 = bf16 hi/lo
// ---------------------------------------------------------------------------
static constexpr int BK = 32;
static constexpr int ROWB = 80;             // 32 bf16 payload padded to 80B
static constexpr int TILE_B = 128 * ROWB;   // 10240
static constexpr int STAGE_B = 4 * TILE_B;  // Ahi,Alo,Bhi,Blo = 40960
static constexpr int GEMM_SMEM = 2 * STAGE_B;  // 81920

__device__ __forceinline__ void cp_tile(const __nv_bfloat16* __restrict__ src,
                                        int rowBase, int ld, int k0, uint32_t dst)
{
    const char* s0 = (const char*)(src + (size_t)rowBase * ld + k0);
    #pragma unroll
    for (int i = 0; i < 2; i++) {
        int id = threadIdx.x + i * 256;
        int row = id >> 2, c = id & 3;
        const void* g = s0 + (size_t)row * (ld * 2) + c * 16;
        uint32_t d = dst + row * ROWB + c * 16;
        asm volatile("cp.async.cg.shared.global [%0], [%1], 16;" :: "r"(d), "l"(g));
    }
}

template <int EPI>
__global__ void __launch_bounds__(256, 1) gemm_mma(
    const __nv_bfloat16* __restrict__ Ahi, const __nv_bfloat16* __restrict__ Alo,
    const __nv_bfloat16* __restrict__ Bhi, const __nv_bfloat16* __restrict__ Blo,
    float* __restrict__ Yf, __nv_bfloat16* __restrict__ Yhi, __nv_bfloat16* __restrict__ Ylo,
    const float* __restrict__ bias, const float* __restrict__ resid,
    int K, int ldA, int ldB, int ldY,
    size_t strideA, size_t strideB, size_t strideY)
{
    extern __shared__ char smem[];
    uint32_t sb = smem_u32(smem);
    const int tid = threadIdx.x, lane = tid & 31, wid = tid >> 5;
    const int wm = wid & 1, wn = wid >> 1;
    const int mBase = blockIdx.y * 128, nBase = blockIdx.x * 128;
    const size_t zb = blockIdx.z;
    Ahi += zb * strideA; Alo += zb * strideA;
    Bhi += zb * strideB; Blo += zb * strideB;

    float acc[4][4][4];
    #pragma unroll
    for (int i = 0; i < 4; i++)
        #pragma unroll
        for (int j = 0; j < 4; j++)
            #pragma unroll
            for (int r = 0; r < 4; r++) acc[i][j][r] = 0.f;

    const int nch = K / BK;

    // prologue: chunk 0
    {
        uint32_t st = sb;
        cp_tile(Ahi, mBase, ldA, 0, st);
        cp_tile(Alo, mBase, ldA, 0, st + TILE_B);
        cp_tile(Bhi, nBase, ldB, 0, st + 2 * TILE_B);
        cp_tile(Blo, nBase, ldB, 0, st + 3 * TILE_B);
        asm volatile("cp.async.commit_group;" ::: "memory");
    }

    // per-lane ldmatrix offsets (within a stage)
    const int a_row = wm * 64 + (lane & 15);
    const int a_k   = (lane >> 4) << 3;               // 0 or 8
    const int b_row = wn * 32 + ((lane >> 4) << 3) + (lane & 7);
    const int b_k   = ((lane >> 3) & 1) << 3;
    const uint32_t aoff = (uint32_t)(a_row * ROWB + a_k * 2);
    const uint32_t boff = (uint32_t)(2 * TILE_B + b_row * ROWB + b_k * 2);

    #pragma unroll 1
    for (int c = 0; c < nch; ++c) {
        if (c + 1 < nch) {
            uint32_t st = sb + ((c + 1) & 1) * STAGE_B;
            int k0 = (c + 1) * BK;
            cp_tile(Ahi, mBase, ldA, k0, st);
            cp_tile(Alo, mBase, ldA, k0, st + TILE_B);
            cp_tile(Bhi, nBase, ldB, k0, st + 2 * TILE_B);
            cp_tile(Blo, nBase, ldB, k0, st + 3 * TILE_B);
            asm volatile("cp.async.commit_group;" ::: "memory");
            asm volatile("cp.async.wait_group 1;" ::: "memory");
        } else {
            asm volatile("cp.async.wait_group 0;" ::: "memory");
        }
        __syncthreads();

        uint32_t st = sb + (c & 1) * STAGE_B;
        #pragma unroll
        for (int ks = 0; ks < 2; ++ks) {
            uint32_t ah[4][4], al[4][4], bh[4][2], bl[4][2];
            #pragma unroll
            for (int mi = 0; mi < 4; mi++) {
                ldm4(ah[mi], st + aoff + mi * 16 * ROWB + ks * 32);
                ldm4(al[mi], st + TILE_B + aoff + mi * 16 * ROWB + ks * 32);
            }
            #pragma unroll
            for (int nt = 0; nt < 2; nt++) {
                uint32_t r[4];
                ldm4(r, st + boff + nt * 16 * ROWB + ks * 32);
                bh[2*nt][0] = r[0]; bh[2*nt][1] = r[1];
                bh[2*nt+1][0] = r[2]; bh[2*nt+1][1] = r[3];
                ldm4(r, st + TILE_B + boff + nt * 16 * ROWB + ks * 32);
                bl[2*nt][0] = r[0]; bl[2*nt][1] = r[1];
                bl[2*nt+1][0] = r[2]; bl[2*nt+1][1] = r[3];
            }
            #pragma unroll
            for (int mi = 0; mi < 4; mi++)
                #pragma unroll
                for (int ni = 0; ni < 4; ni++) {
                    mma16816(acc[mi][ni], ah[mi], bh[ni]);
                    mma16816(acc[mi][ni], ah[mi], bl[ni]);
                    mma16816(acc[mi][ni], al[mi], bh[ni]);
                }
        }
        __syncthreads();
    }

    // ---- epilogue ----
    const int gid = lane >> 2, tig = lane & 3;
    #pragma unroll
    for (int mi = 0; mi < 4; mi++) {
        int m0 = mBase + wm * 64 + mi * 16 + gid;
        float bM0 = 0.f, bM8 = 0.f;
        if (EPI == 1 || EPI == 3) { bM0 = bias[m0]; bM8 = bias[m0 + 8]; }
        #pragma unroll
        for (int ni = 0; ni < 4; ni++) {
            int n0 = nBase + wn * 32 + ni * 8 + tig * 2;
            float* d = acc[mi][ni];
            size_t off0 = (size_t)m0 * ldY + n0 + zb * strideY;
            size_t off8 = off0 + 8 * (size_t)ldY;
            if (EPI == 0 || EPI == 1) {
                float2 v0 = make_float2(d[0], d[1]);
                float2 v1 = make_float2(d[2], d[3]);
                if (EPI == 1) {
                    v0.x += bM0; v0.y += bM0; v1.x += bM8; v1.y += bM8;
                    float2 r0 = *(const float2*)(resid + off0);
                    float2 r1 = *(const float2*)(resid + off8);
                    v0.x += r0.x; v0.y += r0.y; v1.x += r1.x; v1.y += r1.y;
                }
                *(float2*)(Yf + off0) = v0;
                *(float2*)(Yf + off8) = v1;
            } else {
                float v00 = d[0], v01 = d[1], v10 = d[2], v11 = d[3];
                if (EPI == 2) {
                    float bn0 = bias[n0], bn1 = bias[n0 + 1];
                    v00 += bn0; v01 += bn1; v10 += bn0; v11 += bn1;
                }
                if (EPI == 3) { v00 += bM0; v01 += bM0; v10 += bM8; v11 += bM8; }
                __nv_bfloat16 h00 = __float2bfloat16(v00), h01 = __float2bfloat16(v01);
                __nv_bfloat16 h10 = __float2bfloat16(v10), h11 = __float2bfloat16(v11);
                *(__nv_bfloat162*)(Yhi + off0) = __halves2bfloat162(h00, h01);
                *(__nv_bfloat162*)(Yhi + off8) = __halves2bfloat162(h10, h11);
                *(__nv_bfloat162*)(Ylo + off0) = __halves2bfloat162(
                    __float2bfloat16(v00 - __bfloat162float(h00)),
                    __float2bfloat16(v01 - __bfloat162float(h01)));
                *(__nv_bfloat162*)(Ylo + off8) = __halves2bfloat162(
                    __float2bfloat16(v10 - __bfloat162float(h10)),
                    __float2bfloat16(v11 - __bfloat162float(h11)));
            }
        }
    }
}

// ---------------------------------------------------------------------------
// Launch
// ---------------------------------------------------------------------------
extern "C" void kernel_launch(void* const* d_in, const int* in_sizes, int n_in,
                              void* d_out, int out_size)
{
    (void)in_sizes; (void)n_in; (void)out_size;
    const float* f_c   = (const float*)d_in[0];
    const float* f_s   = (const float*)d_in[1];
    const float* W[4]  = { (const float*)d_in[2], (const float*)d_in[4],
                           (const float*)d_in[6], (const float*)d_in[8] };
    const float* b_c1  = (const float*)d_in[3];
    const float* b_s1  = (const float*)d_in[5];
    const float* b_s2  = (const float*)d_in[7];
    const float* b_csc = (const float*)d_in[9];
    float* out = (float*)d_out;

    cudaFuncSetAttribute(gemm_mma<0>, cudaFuncAttributeMaxDynamicSharedMemorySize, GEMM_SMEM);
    cudaFuncSetAttribute(gemm_mma<1>, cudaFuncAttributeMaxDynamicSharedMemorySize, GEMM_SMEM);
    cudaFuncSetAttribute(gemm_mma<2>, cudaFuncAttributeMaxDynamicSharedMemorySize, GEMM_SMEM);
    cudaFuncSetAttribute(gemm_mma<3>, cudaFuncAttributeMaxDynamicSharedMemorySize, GEMM_SMEM);
    cudaFuncSetAttribute(gemm_mma<4>, cudaFuncAttributeMaxDynamicSharedMemorySize, GEMM_SMEM);

    float *stats, *scores;
    __nv_bfloat16 *xcT_hi, *xcT_lo, *xsT_hi, *xsT_lo, *W_hi, *W_lo;
    __nv_bfloat16 *qt_hi, *qt_lo, *kt_hi, *kt_lo, *h_hi, *h_lo;
    __nv_bfloat16 *o2t_hi, *o2t_lo, *att_hi, *att_lo;
    cudaGetSymbolAddress((void**)&stats,  g_stats);
    cudaGetSymbolAddress((void**)&xcT_hi, g_xcT_hi); cudaGetSymbolAddress((void**)&xcT_lo, g_xcT_lo);
    cudaGetSymbolAddress((void**)&xsT_hi, g_xsT_hi); cudaGetSymbolAddress((void**)&xsT_lo, g_xsT_lo);
    cudaGetSymbolAddress((void**)&W_hi,   g_W_hi);   cudaGetSymbolAddress((void**)&W_lo,   g_W_lo);
    cudaGetSymbolAddress((void**)&qt_hi,  g_qt_hi);  cudaGetSymbolAddress((void**)&qt_lo,  g_qt_lo);
    cudaGetSymbolAddress((void**)&kt_hi,  g_kt_hi);  cudaGetSymbolAddress((void**)&kt_lo,  g_kt_lo);
    cudaGetSymbolAddress((void**)&h_hi,   g_h_hi);   cudaGetSymbolAddress((void**)&h_lo,   g_h_lo);
    cudaGetSymbolAddress((void**)&o2t_hi, g_o2t_hi); cudaGetSymbolAddress((void**)&o2t_lo, g_o2t_lo);
    cudaGetSymbolAddress((void**)&scores, g_scores);
    cudaGetSymbolAddress((void**)&att_hi, g_att_hi); cudaGetSymbolAddress((void**)&att_lo, g_att_lo);

    const size_t sNC = (size_t)NN * CC;
    const size_t sNN = (size_t)NN * NN;

    // 1) norm stats + normalize/transpose/split
    stats_kernel<<<BB * CC, 256>>>(f_c, stats);
    {
        dim3 g(NN / 32, CC / 32, BB);
        norm_tsplit_kernel<<<g, 256>>>(f_c, stats, xcT_hi, xcT_lo);
    }
    stats_kernel<<<BB * CC, 256>>>(f_s, stats);
    {
        dim3 g(NN / 32, CC / 32, BB);
        norm_tsplit_kernel<<<g, 256>>>(f_s, stats, xsT_hi, xsT_lo);
    }

    // 2) weight splits
    for (int i = 0; i < 4; i++)
        split_kernel<<<(CC * CC + 255) / 256, 256>>>(W[i], W_hi + (size_t)i * CC * CC,
                                                     W_lo + (size_t)i * CC * CC, CC * CC);

    // 3) Qt[n,o] = xcT . W_c1^T + b_c1[o] ; Kt[n,o] = xsT . W_s1^T + b_s1[o]
    {
        dim3 g(CC / 128, NN / 128, BB);
        gemm_mma<2><<<g, 256, GEMM_SMEM>>>(xcT_hi, xcT_lo, W_hi + 0 * CC * CC, W_lo + 0 * CC * CC,
                                           nullptr, qt_hi, qt_lo, b_c1, nullptr,
                                           CC, CC, CC, CC, sNC, 0, sNC);
        gemm_mma<2><<<g, 256, GEMM_SMEM>>>(xsT_hi, xsT_lo, W_hi + 1 * CC * CC, W_lo + 1 * CC * CC,
                                           nullptr, kt_hi, kt_lo, b_s1, nullptr,
                                           CC, CC, CC, CC, sNC, 0, sNC);
    }
    // 4) h[o,n] = W_s2 . xsT^T + b_s2[o]
    {
        dim3 g(NN / 128, CC / 128, BB);
        gemm_mma<3><<<g, 256, GEMM_SMEM>>>(W_hi + 2 * CC * CC, W_lo + 2 * CC * CC, xsT_hi, xsT_lo,
                                           nullptr, h_hi, h_lo, b_s2, nullptr,
                                           CC, CC, CC, NN, 0, sNC, sNC);
    }
    // 5) scores[i,j] = Qt . Kt^T (fp32)
    {
        dim3 g(NN / 128, NN / 128, BB);
        gemm_mma<0><<<g, 256, GEMM_SMEM>>>(qt_hi, qt_lo, kt_hi, kt_lo,
                                           scores, nullptr, nullptr, nullptr, nullptr,
                                           CC, CC, CC, NN, sNC, sNC, sNN);
    }
    // 6) softmax -> att hi/lo
    softmax_kernel<<<BB * NN, 256>>>(scores, att_hi, att_lo);

    // 7) o2t[i,c] = att . h^T
    {
        dim3 g(CC / 128, NN / 128, BB);
        gemm_mma<4><<<g, 256, GEMM_SMEM>>>(att_hi, att_lo, h_hi, h_lo,
                                           nullptr, o2t_hi, o2t_lo, nullptr, nullptr,
                                           NN, NN, NN, CC, sNN, sNC, sNC);
    }
    // 8) out[o,n] = W_csc . o2t^T + b_csc[o] + f_c
    {
        dim3 g(NN / 128, CC / 128, BB);
        gemm_mma<1><<<g, 256, GEMM_SMEM>>>(W_hi + 3 * CC * CC, W_lo + 3 * CC * CC, o2t_hi, o2t_lo,
                                           out, nullptr, nullptr, b_csc, f_c,
                                           CC, CC, CC, NN, 0, sNC, sNC);
    }
}

// round 7
// speedup vs baseline: 2.6288x; 1.0982x over previous
#include <cuda_runtime.h>
#include <cuda_bf16.h>
#include <cstdint>
#include <cstddef>

#define BB 4
#define CC 512
#define NN 4096

// ---------------------------------------------------------------------------
// Scratch (allocation-free rule -> __device__ globals)
// ---------------------------------------------------------------------------
__device__ float g_stats[BB * CC * 2];
__device__ __nv_bfloat16 g_xcT_hi[(size_t)BB * NN * CC], g_xcT_lo[(size_t)BB * NN * CC];
__device__ __nv_bfloat16 g_xsT_hi[(size_t)BB * NN * CC], g_xsT_lo[(size_t)BB * NN * CC];
__device__ __nv_bfloat16 g_W_hi[4][CC * CC], g_W_lo[4][CC * CC];
__device__ __nv_bfloat16 g_qt_hi[(size_t)BB * NN * CC], g_qt_lo[(size_t)BB * NN * CC];
__device__ __nv_bfloat16 g_kt_hi[(size_t)BB * NN * CC], g_kt_lo[(size_t)BB * NN * CC];
__device__ __nv_bfloat16 g_h_hi[(size_t)BB * CC * NN],  g_h_lo[(size_t)BB * CC * NN];
__device__ __nv_bfloat16 g_o2t_hi[(size_t)BB * NN * CC], g_o2t_lo[(size_t)BB * NN * CC];
__device__ float g_scores[(size_t)BB * NN * NN];
__device__ __nv_bfloat16 g_att_hi[(size_t)BB * NN * NN], g_att_lo[(size_t)BB * NN * NN];

// ---------------------------------------------------------------------------
// helpers
// ---------------------------------------------------------------------------
__device__ __forceinline__ uint32_t smem_u32(const void* p) {
    uint32_t a;
    asm("{ .reg .u64 t; cvta.to.shared.u64 t, %1; cvt.u32.u64 %0, t; }" : "=r"(a) : "l"(p));
    return a;
}

__device__ __forceinline__ void ldm4(uint32_t* r, uint32_t addr) {
    asm volatile("ldmatrix.sync.aligned.m8n8.x4.shared.b16 {%0,%1,%2,%3}, [%4];"
        : "=r"(r[0]), "=r"(r[1]), "=r"(r[2]), "=r"(r[3]) : "r"(addr));
}

__device__ __forceinline__ void mma16816(float* d, const uint32_t* a, const uint32_t* b) {
    asm volatile("mma.sync.aligned.m16n8k16.row.col.f32.bf16.bf16.f32 "
        "{%0,%1,%2,%3}, {%4,%5,%6,%7}, {%8,%9}, {%0,%1,%2,%3};"
        : "+f"(d[0]), "+f"(d[1]), "+f"(d[2]), "+f"(d[3])
        : "r"(a[0]), "r"(a[1]), "r"(a[2]), "r"(a[3]), "r"(b[0]), "r"(b[1]));
}

// ---------------------------------------------------------------------------
// Norm stats: one block per (b,c) row (ddof=1, eps=1e-5)
// ---------------------------------------------------------------------------
__global__ void __launch_bounds__(256) stats_kernel(const float* __restrict__ x,
                                                    float* __restrict__ stats)
{
    const float* row = x + (size_t)blockIdx.x * NN;
    float s = 0.f, s2 = 0.f;
    #pragma unroll 4
    for (int i = threadIdx.x; i < NN; i += 256) { float v = row[i]; s += v; s2 += v * v; }
    __shared__ float red[64];
    #pragma unroll
    for (int o = 16; o; o >>= 1) {
        s  += __shfl_xor_sync(0xffffffffu, s,  o);
        s2 += __shfl_xor_sync(0xffffffffu, s2, o);
    }
    int w = threadIdx.x >> 5;
    if ((threadIdx.x & 31) == 0) { red[w] = s; red[32 + w] = s2; }
    __syncthreads();
    if (threadIdx.x == 0) {
        float ts = 0.f, ts2 = 0.f;
        #pragma unroll
        for (int i = 0; i < 8; i++) { ts += red[i]; ts2 += red[32 + i]; }
        float mean = ts * (1.0f / NN);
        float var = (ts2 - (float)NN * mean * mean) * (1.0f / (NN - 1));
        stats[blockIdx.x * 2]     = mean;
        stats[blockIdx.x * 2 + 1] = rsqrtf(var + 1e-5f);
    }
}

// ---------------------------------------------------------------------------
// Normalize + transpose ([B,C,N] -> [B,N,C]) + bf16 hi/lo split
// ---------------------------------------------------------------------------
__global__ void __launch_bounds__(256) norm_tsplit_kernel(
    const float* __restrict__ x, const float* __restrict__ stats,
    __nv_bfloat16* __restrict__ hiT, __nv_bfloat16* __restrict__ loT)
{
    __shared__ float tile[32][33];
    int b = blockIdx.z, c0 = blockIdx.y * 32, n0 = blockIdx.x * 32;
    int tx = threadIdx.x & 31, ty = threadIdx.x >> 5;
    #pragma unroll
    for (int p = 0; p < 4; p++) {
        int ci = p * 8 + ty;
        int si = (b * CC + c0 + ci) * 2;
        float mean = stats[si], inv = stats[si + 1];
        float v = x[((size_t)(b * CC + c0 + ci)) * NN + n0 + tx];
        tile[ci][tx] = (v - mean) * inv;
    }
    __syncthreads();
    #pragma unroll
    for (int p = 0; p < 4; p++) {
        int ni = p * 8 + ty;
        float v = tile[tx][ni];
        __nv_bfloat16 h = __float2bfloat16(v);
        __nv_bfloat16 l = __float2bfloat16(v - __bfloat162float(h));
        size_t o = ((size_t)b * NN + n0 + ni) * CC + c0 + tx;
        hiT[o] = h; loT[o] = l;
    }
}

__global__ void __launch_bounds__(256) split_kernel(const float* __restrict__ w,
                                                    __nv_bfloat16* __restrict__ hi,
                                                    __nv_bfloat16* __restrict__ lo, int n)
{
    int i = blockIdx.x * 256 + threadIdx.x;
    if (i < n) {
        float v = w[i];
        __nv_bfloat16 h = __float2bfloat16(v);
        hi[i] = h; lo[i] = __float2bfloat16(v - __bfloat162float(h));
    }
}

// ---------------------------------------------------------------------------
// Row softmax (4096) -> bf16 hi/lo attention
// ---------------------------------------------------------------------------
__global__ void __launch_bounds__(256) softmax_kernel(const float* __restrict__ S,
                                                      __nv_bfloat16* __restrict__ Ahi,
                                                      __nv_bfloat16* __restrict__ Alo)
{
    const float* row = S + (size_t)blockIdx.x * NN;
    float v[16];
    float mx = -1e30f;
    #pragma unroll
    for (int j = 0; j < 16; j++) { v[j] = row[threadIdx.x + j * 256]; mx = fmaxf(mx, v[j]); }
    __shared__ float red[8];
    #pragma unroll
    for (int o = 16; o; o >>= 1) mx = fmaxf(mx, __shfl_xor_sync(0xffffffffu, mx, o));
    if ((threadIdx.x & 31) == 0) red[threadIdx.x >> 5] = mx;
    __syncthreads();
    mx = red[0];
    #pragma unroll
    for (int i = 1; i < 8; i++) mx = fmaxf(mx, red[i]);
    __syncthreads();
    float sum = 0.f;
    #pragma unroll
    for (int j = 0; j < 16; j++) { v[j] = expf(v[j] - mx); sum += v[j]; }
    #pragma unroll
    for (int o = 16; o; o >>= 1) sum += __shfl_xor_sync(0xffffffffu, sum, o);
    if ((threadIdx.x & 31) == 0) red[threadIdx.x >> 5] = sum;
    __syncthreads();
    sum = 0.f;
    #pragma unroll
    for (int i = 0; i < 8; i++) sum += red[i];
    float inv = 1.0f / sum;
    size_t base = (size_t)blockIdx.x * NN + threadIdx.x;
    #pragma unroll
    for (int j = 0; j < 16; j++) {
        float p = v[j] * inv;
        __nv_bfloat16 h = __float2bfloat16(p);
        Ahi[base + j * 256] = h;
        Alo[base + j * 256] = __float2bfloat16(p - __bfloat162float(h));
    }
}

// ---------------------------------------------------------------------------
// HMMA split-bf16 GEMM:  D[M,N] = (Ahi+Alo)[M,K] . (Bhi+Blo)[N,K]^T
// CTA tile 128(M) x 256(N), BK=32, 3-stage cp.async, mma.sync m16n8k16.
// 8 warps: warp (wm = wid&1, wn = wid>>1) owns a 64(M) x 64(N) sub-tile.
// EPI: 0 = fp32 out             1 = fp32 out + bias[m] + resid
//      2 = bf16 hi/lo + bias[n] 3 = bf16 hi/lo + bias[m]  4 = bf16 hi/lo
// ---------------------------------------------------------------------------
static constexpr int BK = 32;
static constexpr int ROWB = 80;                   // 32 bf16 payload padded to 80B
static constexpr int A_TILE_B = 128 * ROWB;       // 10240 (one of hi/lo)
static constexpr int B_TILE_B = 256 * ROWB;       // 20480
static constexpr int B_REGION = 2 * A_TILE_B;     // offset of B within a stage
static constexpr int STAGE_B = 2 * A_TILE_B + 2 * B_TILE_B;   // 61440
static constexpr int NSTAGE = 3;
static constexpr int GEMM_SMEM = NSTAGE * STAGE_B;            // 184320

template <int ROWS, int NCP>
__device__ __forceinline__ void cp_tile(const __nv_bfloat16* __restrict__ src,
                                        int rowBase, int ld, int k0, uint32_t dst)
{
    const char* s0 = (const char*)(src + (size_t)rowBase * ld + k0);
    #pragma unroll
    for (int i = 0; i < NCP; i++) {
        int id = threadIdx.x + i * 256;
        int row = id >> 2, c = id & 3;
        const void* g = s0 + (size_t)row * (ld * 2) + c * 16;
        uint32_t d = dst + row * ROWB + c * 16;
        asm volatile("cp.async.cg.shared.global [%0], [%1], 16;" :: "r"(d), "l"(g));
    }
}

template <int EPI>
__global__ void __launch_bounds__(256, 1) gemm_mma(
    const __nv_bfloat16* __restrict__ Ahi, const __nv_bfloat16* __restrict__ Alo,
    const __nv_bfloat16* __restrict__ Bhi, const __nv_bfloat16* __restrict__ Blo,
    float* __restrict__ Yf, __nv_bfloat16* __restrict__ Yhi, __nv_bfloat16* __restrict__ Ylo,
    const float* __restrict__ bias, const float* __restrict__ resid,
    int K, int ldA, int ldB, int ldY,
    size_t strideA, size_t strideB, size_t strideY)
{
    extern __shared__ char smem[];
    uint32_t sb = smem_u32(smem);
    const int tid = threadIdx.x, lane = tid & 31, wid = tid >> 5;
    const int wm = wid & 1, wn = wid >> 1;
    const int mBase = blockIdx.y * 128, nBase = blockIdx.x * 256;
    const size_t zb = blockIdx.z;
    Ahi += zb * strideA; Alo += zb * strideA;
    Bhi += zb * strideB; Blo += zb * strideB;

    float acc[4][8][4];
    #pragma unroll
    for (int i = 0; i < 4; i++)
        #pragma unroll
        for (int j = 0; j < 8; j++)
            #pragma unroll
            for (int r = 0; r < 4; r++) acc[i][j][r] = 0.f;

    const int nch = K / BK;

    // prologue: stages 0,1
    #pragma unroll
    for (int c = 0; c < 2; ++c) {
        uint32_t st = sb + c * STAGE_B;
        int k0 = c * BK;
        cp_tile<128, 2>(Ahi, mBase, ldA, k0, st);
        cp_tile<128, 2>(Alo, mBase, ldA, k0, st + A_TILE_B);
        cp_tile<256, 4>(Bhi, nBase, ldB, k0, st + B_REGION);
        cp_tile<256, 4>(Blo, nBase, ldB, k0, st + B_REGION + B_TILE_B);
        asm volatile("cp.async.commit_group;" ::: "memory");
    }

    // per-lane ldmatrix offsets (within a stage)
    const int a_row = wm * 64 + (lane & 15);
    const int a_k   = (lane >> 4) << 3;                 // 0 or 8
    const int b_row = wn * 64 + ((lane >> 4) << 3) + (lane & 7);
    const int b_k   = ((lane >> 3) & 1) << 3;
    const uint32_t aoff = (uint32_t)(a_row * ROWB + a_k * 2);
    const uint32_t boff = (uint32_t)(B_REGION + b_row * ROWB + b_k * 2);

    #pragma unroll 1
    for (int c = 0; c < nch; ++c) {
        if (c + 2 < nch) {
            uint32_t st = sb + ((c + 2) % NSTAGE) * STAGE_B;
            int k0 = (c + 2) * BK;
            cp_tile<128, 2>(Ahi, mBase, ldA, k0, st);
            cp_tile<128, 2>(Alo, mBase, ldA, k0, st + A_TILE_B);
            cp_tile<256, 4>(Bhi, nBase, ldB, k0, st + B_REGION);
            cp_tile<256, 4>(Blo, nBase, ldB, k0, st + B_REGION + B_TILE_B);
            asm volatile("cp.async.commit_group;" ::: "memory");
            asm volatile("cp.async.wait_group 2;" ::: "memory");
        } else if (c + 1 < nch) {
            asm volatile("cp.async.wait_group 1;" ::: "memory");
        } else {
            asm volatile("cp.async.wait_group 0;" ::: "memory");
        }
        __syncthreads();

        uint32_t st = sb + (c % NSTAGE) * STAGE_B;
        #pragma unroll
        for (int ks = 0; ks < 2; ++ks) {
            uint32_t ah[4][4], al[4][4];
            #pragma unroll
            for (int mi = 0; mi < 4; mi++) {
                ldm4(ah[mi], st + aoff + mi * 16 * ROWB + ks * 32);
                ldm4(al[mi], st + A_TILE_B + aoff + mi * 16 * ROWB + ks * 32);
            }
            #pragma unroll
            for (int nt = 0; nt < 4; nt++) {
                uint32_t rh[4], rl[4];
                ldm4(rh, st + boff + nt * 16 * ROWB + ks * 32);
                ldm4(rl, st + B_TILE_B + boff + nt * 16 * ROWB + ks * 32);
                #pragma unroll
                for (int half = 0; half < 2; half++) {
                    uint32_t bh[2] = { rh[2 * half], rh[2 * half + 1] };
                    uint32_t bl[2] = { rl[2 * half], rl[2 * half + 1] };
                    int ni = 2 * nt + half;
                    #pragma unroll
                    for (int mi = 0; mi < 4; mi++) {
                        mma16816(acc[mi][ni], ah[mi], bh);
                        mma16816(acc[mi][ni], ah[mi], bl);
                        mma16816(acc[mi][ni], al[mi], bh);
                    }
                }
            }
        }
        __syncthreads();
    }

    // ---- epilogue ----
    const int gid = lane >> 2, tig = lane & 3;
    #pragma unroll
    for (int mi = 0; mi < 4; mi++) {
        int m0 = mBase + wm * 64 + mi * 16 + gid;
        float bM0 = 0.f, bM8 = 0.f;
        if (EPI == 1 || EPI == 3) { bM0 = bias[m0]; bM8 = bias[m0 + 8]; }
        #pragma unroll
        for (int ni = 0; ni < 8; ni++) {
            int n0 = nBase + wn * 64 + ni * 8 + tig * 2;
            float* d = acc[mi][ni];
            size_t off0 = (size_t)m0 * ldY + n0 + zb * strideY;
            size_t off8 = off0 + 8 * (size_t)ldY;
            if (EPI == 0 || EPI == 1) {
                float2 v0 = make_float2(d[0], d[1]);
                float2 v1 = make_float2(d[2], d[3]);
                if (EPI == 1) {
                    v0.x += bM0; v0.y += bM0; v1.x += bM8; v1.y += bM8;
                    float2 r0 = *(const float2*)(resid + off0);
                    float2 r1 = *(const float2*)(resid + off8);
                    v0.x += r0.x; v0.y += r0.y; v1.x += r1.x; v1.y += r1.y;
                }
                *(float2*)(Yf + off0) = v0;
                *(float2*)(Yf + off8) = v1;
            } else {
                float v00 = d[0], v01 = d[1], v10 = d[2], v11 = d[3];
                if (EPI == 2) {
                    float bn0 = bias[n0], bn1 = bias[n0 + 1];
                    v00 += bn0; v01 += bn1; v10 += bn0; v11 += bn1;
                }
                if (EPI == 3) { v00 += bM0; v01 += bM0; v10 += bM8; v11 += bM8; }
                __nv_bfloat16 h00 = __float2bfloat16(v00), h01 = __float2bfloat16(v01);
                __nv_bfloat16 h10 = __float2bfloat16(v10), h11 = __float2bfloat16(v11);
                *(__nv_bfloat162*)(Yhi + off0) = __halves2bfloat162(h00, h01);
                *(__nv_bfloat162*)(Yhi + off8) = __halves2bfloat162(h10, h11);
                *(__nv_bfloat162*)(Ylo + off0) = __halves2bfloat162(
                    __float2bfloat16(v00 - __bfloat162float(h00)),
                    __float2bfloat16(v01 - __bfloat162float(h01)));
                *(__nv_bfloat162*)(Ylo + off8) = __halves2bfloat162(
                    __float2bfloat16(v10 - __bfloat162float(h10)),
                    __float2bfloat16(v11 - __bfloat162float(h11)));
            }
        }
    }
}

// ---------------------------------------------------------------------------
// Launch
// ---------------------------------------------------------------------------
extern "C" void kernel_launch(void* const* d_in, const int* in_sizes, int n_in,
                              void* d_out, int out_size)
{
    (void)in_sizes; (void)n_in; (void)out_size;
    const float* f_c   = (const float*)d_in[0];
    const float* f_s   = (const float*)d_in[1];
    const float* W[4]  = { (const float*)d_in[2], (const float*)d_in[4],
                           (const float*)d_in[6], (const float*)d_in[8] };
    const float* b_c1  = (const float*)d_in[3];
    const float* b_s1  = (const float*)d_in[5];
    const float* b_s2  = (const float*)d_in[7];
    const float* b_csc = (const float*)d_in[9];
    float* out = (float*)d_out;

    cudaFuncSetAttribute(gemm_mma<0>, cudaFuncAttributeMaxDynamicSharedMemorySize, GEMM_SMEM);
    cudaFuncSetAttribute(gemm_mma<1>, cudaFuncAttributeMaxDynamicSharedMemorySize, GEMM_SMEM);
    cudaFuncSetAttribute(gemm_mma<2>, cudaFuncAttributeMaxDynamicSharedMemorySize, GEMM_SMEM);
    cudaFuncSetAttribute(gemm_mma<3>, cudaFuncAttributeMaxDynamicSharedMemorySize, GEMM_SMEM);
    cudaFuncSetAttribute(gemm_mma<4>, cudaFuncAttributeMaxDynamicSharedMemorySize, GEMM_SMEM);

    float *stats, *scores;
    __nv_bfloat16 *xcT_hi, *xcT_lo, *xsT_hi, *xsT_lo, *W_hi, *W_lo;
    __nv_bfloat16 *qt_hi, *qt_lo, *kt_hi, *kt_lo, *h_hi, *h_lo;
    __nv_bfloat16 *o2t_hi, *o2t_lo, *att_hi, *att_lo;
    cudaGetSymbolAddress((void**)&stats,  g_stats);
    cudaGetSymbolAddress((void**)&xcT_hi, g_xcT_hi); cudaGetSymbolAddress((void**)&xcT_lo, g_xcT_lo);
    cudaGetSymbolAddress((void**)&xsT_hi, g_xsT_hi); cudaGetSymbolAddress((void**)&xsT_lo, g_xsT_lo);
    cudaGetSymbolAddress((void**)&W_hi,   g_W_hi);   cudaGetSymbolAddress((void**)&W_lo,   g_W_lo);
    cudaGetSymbolAddress((void**)&qt_hi,  g_qt_hi);  cudaGetSymbolAddress((void**)&qt_lo,  g_qt_lo);
    cudaGetSymbolAddress((void**)&kt_hi,  g_kt_hi);  cudaGetSymbolAddress((void**)&kt_lo,  g_kt_lo);
    cudaGetSymbolAddress((void**)&h_hi,   g_h_hi);   cudaGetSymbolAddress((void**)&h_lo,   g_h_lo);
    cudaGetSymbolAddress((void**)&o2t_hi, g_o2t_hi); cudaGetSymbolAddress((void**)&o2t_lo, g_o2t_lo);
    cudaGetSymbolAddress((void**)&scores, g_scores);
    cudaGetSymbolAddress((void**)&att_hi, g_att_hi); cudaGetSymbolAddress((void**)&att_lo, g_att_lo);

    const size_t sNC = (size_t)NN * CC;
    const size_t sNN = (size_t)NN * NN;

    // 1) norm stats + normalize/transpose/split
    stats_kernel<<<BB * CC, 256>>>(f_c, stats);
    {
        dim3 g(NN / 32, CC / 32, BB);
        norm_tsplit_kernel<<<g, 256>>>(f_c, stats, xcT_hi, xcT_lo);
    }
    stats_kernel<<<BB * CC, 256>>>(f_s, stats);
    {
        dim3 g(NN / 32, CC / 32, BB);
        norm_tsplit_kernel<<<g, 256>>>(f_s, stats, xsT_hi, xsT_lo);
    }

    // 2) weight splits
    for (int i = 0; i < 4; i++)
        split_kernel<<<(CC * CC + 255) / 256, 256>>>(W[i], W_hi + (size_t)i * CC * CC,
                                                     W_lo + (size_t)i * CC * CC, CC * CC);

    // 3) Qt[n,o] = xcT . W_c1^T + b_c1[o] ; Kt[n,o] = xsT . W_s1^T + b_s1[o]
    {
        dim3 g(CC / 256, NN / 128, BB);   // (2, 32, 4)
        gemm_mma<2><<<g, 256, GEMM_SMEM>>>(xcT_hi, xcT_lo, W_hi + 0 * CC * CC, W_lo + 0 * CC * CC,
                                           nullptr, qt_hi, qt_lo, b_c1, nullptr,
                                           CC, CC, CC, CC, sNC, 0, sNC);
        gemm_mma<2><<<g, 256, GEMM_SMEM>>>(xsT_hi, xsT_lo, W_hi + 1 * CC * CC, W_lo + 1 * CC * CC,
                                           nullptr, kt_hi, kt_lo, b_s1, nullptr,
                                           CC, CC, CC, CC, sNC, 0, sNC);
    }
    // 4) h[o,n] = W_s2 . xsT^T + b_s2[o]
    {
        dim3 g(NN / 256, CC / 128, BB);   // (16, 4, 4)
        gemm_mma<3><<<g, 256, GEMM_SMEM>>>(W_hi + 2 * CC * CC, W_lo + 2 * CC * CC, xsT_hi, xsT_lo,
                                           nullptr, h_hi, h_lo, b_s2, nullptr,
                                           CC, CC, CC, NN, 0, sNC, sNC);
    }
    // 5) scores[i,j] = Qt . Kt^T (fp32)
    {
        dim3 g(NN / 256, NN / 128, BB);   // (16, 32, 4)
        gemm_mma<0><<<g, 256, GEMM_SMEM>>>(qt_hi, qt_lo, kt_hi, kt_lo,
                                           scores, nullptr, nullptr, nullptr, nullptr,
                                           CC, CC, CC, NN, sNC, sNC, sNN);
    }
    // 6) softmax -> att hi/lo
    softmax_kernel<<<BB * NN, 256>>>(scores, att_hi, att_lo);

    // 7) o2t[i,c] = att . h^T
    {
        dim3 g(CC / 256, NN / 128, BB);   // (2, 32, 4)
        gemm_mma<4><<<g, 256, GEMM_SMEM>>>(att_hi, att_lo, h_hi, h_lo,
                                           nullptr, o2t_hi, o2t_lo, nullptr, nullptr,
                                           NN, NN, NN, CC, sNN, sNC, sNC);
    }
    // 8) out[o,n] = W_csc . o2t^T + b_csc[o] + f_c
    {
        dim3 g(NN / 256, CC / 128, BB);   // (16, 4, 4)
        gemm_mma<1><<<g, 256, GEMM_SMEM>>>(W_hi + 3 * CC * CC, W_lo + 3 * CC * CC, o2t_hi, o2t_lo,
                                           out, nullptr, nullptr, b_csc, f_c,
                                           CC, CC, CC, NN, 0, sNC, sNC);
    }
}

// round 8
// speedup vs baseline: 2.7308x; 1.0388x over previous
#include <cuda_runtime.h>
#include <cuda_bf16.h>
#include <cstdint>
#include <cstddef>

#define BB 4
#define CC 512
#define NN 4096

// ---------------------------------------------------------------------------
// Scratch (allocation-free rule -> __device__ globals)
// ---------------------------------------------------------------------------
__device__ float g_stats[BB * CC * 2];
__device__ __nv_bfloat16 g_xcT_hi[(size_t)BB * NN * CC], g_xcT_lo[(size_t)BB * NN * CC];
__device__ __nv_bfloat16 g_xsT_hi[(size_t)BB * NN * CC], g_xsT_lo[(size_t)BB * NN * CC];
__device__ __nv_bfloat16 g_W_hi[4][CC * CC], g_W_lo[4][CC * CC];
__device__ __nv_bfloat16 g_qt_hi[(size_t)BB * NN * CC], g_qt_lo[(size_t)BB * NN * CC];
__device__ __nv_bfloat16 g_kt_hi[(size_t)BB * NN * CC], g_kt_lo[(size_t)BB * NN * CC];
__device__ __nv_bfloat16 g_h_hi[(size_t)BB * CC * NN],  g_h_lo[(size_t)BB * CC * NN];
__device__ __nv_bfloat16 g_o2t_hi[(size_t)BB * NN * CC], g_o2t_lo[(size_t)BB * NN * CC];
__device__ float g_scores[(size_t)BB * NN * NN];
__device__ __nv_bfloat16 g_att_hi[(size_t)BB * NN * NN], g_att_lo[(size_t)BB * NN * NN];

// ---------------------------------------------------------------------------
// helpers
// ---------------------------------------------------------------------------
__device__ __forceinline__ uint32_t smem_u32(const void* p) {
    uint32_t a;
    asm("{ .reg .u64 t; cvta.to.shared.u64 t, %1; cvt.u32.u64 %0, t; }" : "=r"(a) : "l"(p));
    return a;
}

__device__ __forceinline__ void ldm4(uint32_t* r, uint32_t addr) {
    asm volatile("ldmatrix.sync.aligned.m8n8.x4.shared.b16 {%0,%1,%2,%3}, [%4];"
        : "=r"(r[0]), "=r"(r[1]), "=r"(r[2]), "=r"(r[3]) : "r"(addr));
}

__device__ __forceinline__ void mma16816(float* d, const uint32_t* a, const uint32_t* b) {
    asm volatile("mma.sync.aligned.m16n8k16.row.col.f32.bf16.bf16.f32 "
        "{%0,%1,%2,%3}, {%4,%5,%6,%7}, {%8,%9}, {%0,%1,%2,%3};"
        : "+f"(d[0]), "+f"(d[1]), "+f"(d[2]), "+f"(d[3])
        : "r"(a[0]), "r"(a[1]), "r"(a[2]), "r"(a[3]), "r"(b[0]), "r"(b[1]));
}

// ---------------------------------------------------------------------------
// Norm stats: one block per (b,c) row (ddof=1, eps=1e-5)
// ---------------------------------------------------------------------------
__global__ void __launch_bounds__(256) stats_kernel(const float* __restrict__ x,
                                                    float* __restrict__ stats)
{
    const float* row = x + (size_t)blockIdx.x * NN;
    float s = 0.f, s2 = 0.f;
    #pragma unroll 4
    for (int i = threadIdx.x; i < NN; i += 256) { float v = row[i]; s += v; s2 += v * v; }
    __shared__ float red[64];
    #pragma unroll
    for (int o = 16; o; o >>= 1) {
        s  += __shfl_xor_sync(0xffffffffu, s,  o);
        s2 += __shfl_xor_sync(0xffffffffu, s2, o);
    }
    int w = threadIdx.x >> 5;
    if ((threadIdx.x & 31) == 0) { red[w] = s; red[32 + w] = s2; }
    __syncthreads();
    if (threadIdx.x == 0) {
        float ts = 0.f, ts2 = 0.f;
        #pragma unroll
        for (int i = 0; i < 8; i++) { ts += red[i]; ts2 += red[32 + i]; }
        float mean = ts * (1.0f / NN);
        float var = (ts2 - (float)NN * mean * mean) * (1.0f / (NN - 1));
        stats[blockIdx.x * 2]     = mean;
        stats[blockIdx.x * 2 + 1] = rsqrtf(var + 1e-5f);
    }
}

// ---------------------------------------------------------------------------
// Normalize + transpose ([B,C,N] -> [B,N,C]) + bf16 hi/lo split
// ---------------------------------------------------------------------------
__global__ void __launch_bounds__(256) norm_tsplit_kernel(
    const float* __restrict__ x, const float* __restrict__ stats,
    __nv_bfloat16* __restrict__ hiT, __nv_bfloat16* __restrict__ loT)
{
    __shared__ float tile[32][33];
    int b = blockIdx.z, c0 = blockIdx.y * 32, n0 = blockIdx.x * 32;
    int tx = threadIdx.x & 31, ty = threadIdx.x >> 5;
    #pragma unroll
    for (int p = 0; p < 4; p++) {
        int ci = p * 8 + ty;
        int si = (b * CC + c0 + ci) * 2;
        float mean = stats[si], inv = stats[si + 1];
        float v = x[((size_t)(b * CC + c0 + ci)) * NN + n0 + tx];
        tile[ci][tx] = (v - mean) * inv;
    }
    __syncthreads();
    #pragma unroll
    for (int p = 0; p < 4; p++) {
        int ni = p * 8 + ty;
        float v = tile[tx][ni];
        __nv_bfloat16 h = __float2bfloat16(v);
        __nv_bfloat16 l = __float2bfloat16(v - __bfloat162float(h));
        size_t o = ((size_t)b * NN + n0 + ni) * CC + c0 + tx;
        hiT[o] = h; loT[o] = l;
    }
}

__global__ void __launch_bounds__(256) split_kernel(const float* __restrict__ w,
                                                    __nv_bfloat16* __restrict__ hi,
                                                    __nv_bfloat16* __restrict__ lo, int n)
{
    int i = blockIdx.x * 256 + threadIdx.x;
    if (i < n) {
        float v = w[i];
        __nv_bfloat16 h = __float2bfloat16(v);
        hi[i] = h; lo[i] = __float2bfloat16(v - __bfloat162float(h));
    }
}

// ---------------------------------------------------------------------------
// Row softmax (4096) -> bf16 hi/lo attention
// ---------------------------------------------------------------------------
__global__ void __launch_bounds__(256) softmax_kernel(const float* __restrict__ S,
                                                      __nv_bfloat16* __restrict__ Ahi,
                                                      __nv_bfloat16* __restrict__ Alo)
{
    const float* row = S + (size_t)blockIdx.x * NN;
    float v[16];
    float mx = -1e30f;
    #pragma unroll
    for (int j = 0; j < 16; j++) { v[j] = row[threadIdx.x + j * 256]; mx = fmaxf(mx, v[j]); }
    __shared__ float red[8];
    #pragma unroll
    for (int o = 16; o; o >>= 1) mx = fmaxf(mx, __shfl_xor_sync(0xffffffffu, mx, o));
    if ((threadIdx.x & 31) == 0) red[threadIdx.x >> 5] = mx;
    __syncthreads();
    mx = red[0];
    #pragma unroll
    for (int i = 1; i < 8; i++) mx = fmaxf(mx, red[i]);
    __syncthreads();
    float sum = 0.f;
    #pragma unroll
    for (int j = 0; j < 16; j++) { v[j] = expf(v[j] - mx); sum += v[j]; }
    #pragma unroll
    for (int o = 16; o; o >>= 1) sum += __shfl_xor_sync(0xffffffffu, sum, o);
    if ((threadIdx.x & 31) == 0) red[threadIdx.x >> 5] = sum;
    __syncthreads();
    sum = 0.f;
    #pragma unroll
    for (int i = 0; i < 8; i++) sum += red[i];
    float inv = 1.0f / sum;
    size_t base = (size_t)blockIdx.x * NN + threadIdx.x;
    #pragma unroll
    for (int j = 0; j < 16; j++) {
        float p = v[j] * inv;
        __nv_bfloat16 h = __float2bfloat16(p);
        Ahi[base + j * 256] = h;
        Alo[base + j * 256] = __float2bfloat16(p - __bfloat162float(h));
    }
}

// ---------------------------------------------------------------------------
// HMMA split-bf16 GEMM:  D[M,N] = (Ahi+Alo)[M,K] . (Bhi+Blo)[N,K]^T
// CTA tile 128(M) x 256(N), BK=32, 3-stage cp.async, one barrier per chunk,
// register double-buffered B fragments. Warp tile 64x64.
// EPI: 0 = fp32 out             1 = fp32 out + bias[m] + resid
//      2 = bf16 hi/lo + bias[n] 3 = bf16 hi/lo + bias[m]  4 = bf16 hi/lo
// ---------------------------------------------------------------------------
static constexpr int BK = 32;
static constexpr int ROWB = 80;                   // 32 bf16 payload padded to 80B
static constexpr int A_TILE_B = 128 * ROWB;       // 10240 (one of hi/lo)
static constexpr int B_TILE_B = 256 * ROWB;       // 20480
static constexpr int B_REGION = 2 * A_TILE_B;
static constexpr int STAGE_B = 2 * A_TILE_B + 2 * B_TILE_B;   // 61440
static constexpr int NSTAGE = 3;
static constexpr int GEMM_SMEM = NSTAGE * STAGE_B;            // 184320

template <int ROWS, int NCP>
__device__ __forceinline__ void cp_tile(const __nv_bfloat16* __restrict__ src,
                                        int rowBase, int ld, int k0, uint32_t dst)
{
    const char* s0 = (const char*)(src + (size_t)rowBase * ld + k0);
    #pragma unroll
    for (int i = 0; i < NCP; i++) {
        int id = threadIdx.x + i * 256;
        int row = id >> 2, c = id & 3;
        const void* g = s0 + (size_t)row * (ld * 2) + c * 16;
        uint32_t d = dst + row * ROWB + c * 16;
        asm volatile("cp.async.cg.shared.global [%0], [%1], 16;" :: "r"(d), "l"(g));
    }
}

template <int EPI>
__global__ void __launch_bounds__(256, 1) gemm_mma(
    const __nv_bfloat16* __restrict__ Ahi, const __nv_bfloat16* __restrict__ Alo,
    const __nv_bfloat16* __restrict__ Bhi, const __nv_bfloat16* __restrict__ Blo,
    float* __restrict__ Yf, __nv_bfloat16* __restrict__ Yhi, __nv_bfloat16* __restrict__ Ylo,
    const float* __restrict__ bias, const float* __restrict__ resid,
    int K, int ldA, int ldB, int ldY,
    size_t strideA, size_t strideB, size_t strideY)
{
    extern __shared__ char smem[];
    uint32_t sb = smem_u32(smem);
    const int tid = threadIdx.x, lane = tid & 31, wid = tid >> 5;
    const int wm = wid & 1, wn = wid >> 1;
    const int mBase = blockIdx.y * 128, nBase = blockIdx.x * 256;
    const size_t zb = blockIdx.z;
    Ahi += zb * strideA; Alo += zb * strideA;
    Bhi += zb * strideB; Blo += zb * strideB;

    float acc[4][8][4];
    #pragma unroll
    for (int i = 0; i < 4; i++)
        #pragma unroll
        for (int j = 0; j < 8; j++)
            #pragma unroll
            for (int r = 0; r < 4; r++) acc[i][j][r] = 0.f;

    const int nch = K / BK;

    // prologue: stages 0,1
    #pragma unroll
    for (int c = 0; c < 2; ++c) {
        uint32_t st = sb + c * STAGE_B;
        int k0 = c * BK;
        cp_tile<128, 2>(Ahi, mBase, ldA, k0, st);
        cp_tile<128, 2>(Alo, mBase, ldA, k0, st + A_TILE_B);
        cp_tile<256, 4>(Bhi, nBase, ldB, k0, st + B_REGION);
        cp_tile<256, 4>(Blo, nBase, ldB, k0, st + B_REGION + B_TILE_B);
        asm volatile("cp.async.commit_group;" ::: "memory");
    }

    // per-lane ldmatrix offsets (within a stage)
    const int a_row = wm * 64 + (lane & 15);
    const int a_k   = (lane >> 4) << 3;                 // 0 or 8
    const int b_row = wn * 64 + ((lane >> 4) << 3) + (lane & 7);
    const int b_k   = ((lane >> 3) & 1) << 3;
    const uint32_t aoff = (uint32_t)(a_row * ROWB + a_k * 2);
    const uint32_t boff = (uint32_t)(B_REGION + b_row * ROWB + b_k * 2);

    #pragma unroll 1
    for (int c = 0; c < nch; ++c) {
        // 1) wait for stage c, single barrier
        if (c + 1 < nch) {
            asm volatile("cp.async.wait_group 1;" ::: "memory");
        } else {
            asm volatile("cp.async.wait_group 0;" ::: "memory");
        }
        __syncthreads();

        // 2) prefetch stage c+2 (safe: all warps finished reading that buffer
        //    in iteration c-1, enforced by the barrier above)
        if (c + 2 < nch) {
            uint32_t stn = sb + ((c + 2) % NSTAGE) * STAGE_B;
            int k0 = (c + 2) * BK;
            cp_tile<128, 2>(Ahi, mBase, ldA, k0, stn);
            cp_tile<128, 2>(Alo, mBase, ldA, k0, stn + A_TILE_B);
            cp_tile<256, 4>(Bhi, nBase, ldB, k0, stn + B_REGION);
            cp_tile<256, 4>(Blo, nBase, ldB, k0, stn + B_REGION + B_TILE_B);
            asm volatile("cp.async.commit_group;" ::: "memory");
        }

        // 3) compute on stage c with register-pipelined fragments
        uint32_t st = sb + (c % NSTAGE) * STAGE_B;
        #pragma unroll
        for (int ks = 0; ks < 2; ++ks) {
            uint32_t ah[4][4], al[4][4];
            #pragma unroll
            for (int mi = 0; mi < 4; mi++) {
                ldm4(ah[mi], st + aoff + mi * 16 * ROWB + ks * 32);
                ldm4(al[mi], st + A_TILE_B + aoff + mi * 16 * ROWB + ks * 32);
            }
            uint32_t bhB[2][4], blB[2][4];
            ldm4(bhB[0], st + boff + ks * 32);
            ldm4(blB[0], st + B_TILE_B + boff + ks * 32);
            #pragma unroll
            for (int nt = 0; nt < 4; nt++) {
                const int cur = nt & 1, nxt = cur ^ 1;
                if (nt < 3) {   // prefetch next B fragments before the MMA burst
                    ldm4(bhB[nxt], st + boff + (nt + 1) * 16 * ROWB + ks * 32);
                    ldm4(blB[nxt], st + B_TILE_B + boff + (nt + 1) * 16 * ROWB + ks * 32);
                }
                #pragma unroll
                for (int half = 0; half < 2; half++) {
                    uint32_t bh[2] = { bhB[cur][2 * half], bhB[cur][2 * half + 1] };
                    uint32_t bl[2] = { blB[cur][2 * half], blB[cur][2 * half + 1] };
                    int ni = 2 * nt + half;
                    #pragma unroll
                    for (int mi = 0; mi < 4; mi++) {
                        mma16816(acc[mi][ni], ah[mi], bh);
                        mma16816(acc[mi][ni], ah[mi], bl);
                        mma16816(acc[mi][ni], al[mi], bh);
                    }
                }
            }
        }
    }

    // ---- epilogue ----
    const int gid = lane >> 2, tig = lane & 3;
    #pragma unroll
    for (int mi = 0; mi < 4; mi++) {
        int m0 = mBase + wm * 64 + mi * 16 + gid;
        float bM0 = 0.f, bM8 = 0.f;
        if (EPI == 1 || EPI == 3) { bM0 = bias[m0]; bM8 = bias[m0 + 8]; }
        #pragma unroll
        for (int ni = 0; ni < 8; ni++) {
            int n0 = nBase + wn * 64 + ni * 8 + tig * 2;
            float* d = acc[mi][ni];
            size_t off0 = (size_t)m0 * ldY + n0 + zb * strideY;
            size_t off8 = off0 + 8 * (size_t)ldY;
            if (EPI == 0 || EPI == 1) {
                float2 v0 = make_float2(d[0], d[1]);
                float2 v1 = make_float2(d[2], d[3]);
                if (EPI == 1) {
                    v0.x += bM0; v0.y += bM0; v1.x += bM8; v1.y += bM8;
                    float2 r0 = *(const float2*)(resid + off0);
                    float2 r1 = *(const float2*)(resid + off8);
                    v0.x += r0.x; v0.y += r0.y; v1.x += r1.x; v1.y += r1.y;
                }
                *(float2*)(Yf + off0) = v0;
                *(float2*)(Yf + off8) = v1;
            } else {
                float v00 = d[0], v01 = d[1], v10 = d[2], v11 = d[3];
                if (EPI == 2) {
                    float bn0 = bias[n0], bn1 = bias[n0 + 1];
                    v00 += bn0; v01 += bn1; v10 += bn0; v11 += bn1;
                }
                if (EPI == 3) { v00 += bM0; v01 += bM0; v10 += bM8; v11 += bM8; }
                __nv_bfloat16 h00 = __float2bfloat16(v00), h01 = __float2bfloat16(v01);
                __nv_bfloat16 h10 = __float2bfloat16(v10), h11 = __float2bfloat16(v11);
                *(__nv_bfloat162*)(Yhi + off0) = __halves2bfloat162(h00, h01);
                *(__nv_bfloat162*)(Yhi + off8) = __halves2bfloat162(h10, h11);
                *(__nv_bfloat162*)(Ylo + off0) = __halves2bfloat162(
                    __float2bfloat16(v00 - __bfloat162float(h00)),
                    __float2bfloat16(v01 - __bfloat162float(h01)));
                *(__nv_bfloat162*)(Ylo + off8) = __halves2bfloat162(
                    __float2bfloat16(v10 - __bfloat162float(h10)),
                    __float2bfloat16(v11 - __bfloat162float(h11)));
            }
        }
    }
}

// ---------------------------------------------------------------------------
// Launch
// ---------------------------------------------------------------------------
extern "C" void kernel_launch(void* const* d_in, const int* in_sizes, int n_in,
                              void* d_out, int out_size)
{
    (void)in_sizes; (void)n_in; (void)out_size;
    const float* f_c   = (const float*)d_in[0];
    const float* f_s   = (const float*)d_in[1];
    const float* W[4]  = { (const float*)d_in[2], (const float*)d_in[4],
                           (const float*)d_in[6], (const float*)d_in[8] };
    const float* b_c1  = (const float*)d_in[3];
    const float* b_s1  = (const float*)d_in[5];
    const float* b_s2  = (const float*)d_in[7];
    const float* b_csc = (const float*)d_in[9];
    float* out = (float*)d_out;

    cudaFuncSetAttribute(gemm_mma<0>, cudaFuncAttributeMaxDynamicSharedMemorySize, GEMM_SMEM);
    cudaFuncSetAttribute(gemm_mma<1>, cudaFuncAttributeMaxDynamicSharedMemorySize, GEMM_SMEM);
    cudaFuncSetAttribute(gemm_mma<2>, cudaFuncAttributeMaxDynamicSharedMemorySize, GEMM_SMEM);
    cudaFuncSetAttribute(gemm_mma<3>, cudaFuncAttributeMaxDynamicSharedMemorySize, GEMM_SMEM);
    cudaFuncSetAttribute(gemm_mma<4>, cudaFuncAttributeMaxDynamicSharedMemorySize, GEMM_SMEM);

    float *stats, *scores;
    __nv_bfloat16 *xcT_hi, *xcT_lo, *xsT_hi, *xsT_lo, *W_hi, *W_lo;
    __nv_bfloat16 *qt_hi, *qt_lo, *kt_hi, *kt_lo, *h_hi, *h_lo;
    __nv_bfloat16 *o2t_hi, *o2t_lo, *att_hi, *att_lo;
    cudaGetSymbolAddress((void**)&stats,  g_stats);
    cudaGetSymbolAddress((void**)&xcT_hi, g_xcT_hi); cudaGetSymbolAddress((void**)&xcT_lo, g_xcT_lo);
    cudaGetSymbolAddress((void**)&xsT_hi, g_xsT_hi); cudaGetSymbolAddress((void**)&xsT_lo, g_xsT_lo);
    cudaGetSymbolAddress((void**)&W_hi,   g_W_hi);   cudaGetSymbolAddress((void**)&W_lo,   g_W_lo);
    cudaGetSymbolAddress((void**)&qt_hi,  g_qt_hi);  cudaGetSymbolAddress((void**)&qt_lo,  g_qt_lo);
    cudaGetSymbolAddress((void**)&kt_hi,  g_kt_hi);  cudaGetSymbolAddress((void**)&kt_lo,  g_kt_lo);
    cudaGetSymbolAddress((void**)&h_hi,   g_h_hi);   cudaGetSymbolAddress((void**)&h_lo,   g_h_lo);
    cudaGetSymbolAddress((void**)&o2t_hi, g_o2t_hi); cudaGetSymbolAddress((void**)&o2t_lo, g_o2t_lo);
    cudaGetSymbolAddress((void**)&scores, g_scores);
    cudaGetSymbolAddress((void**)&att_hi, g_att_hi); cudaGetSymbolAddress((void**)&att_lo, g_att_lo);

    const size_t sNC = (size_t)NN * CC;
    const size_t sNN = (size_t)NN * NN;

    // 1) norm stats + normalize/transpose/split
    stats_kernel<<<BB * CC, 256>>>(f_c, stats);
    {
        dim3 g(NN / 32, CC / 32, BB);
        norm_tsplit_kernel<<<g, 256>>>(f_c, stats, xcT_hi, xcT_lo);
    }
    stats_kernel<<<BB * CC, 256>>>(f_s, stats);
    {
        dim3 g(NN / 32, CC / 32, BB);
        norm_tsplit_kernel<<<g, 256>>>(f_s, stats, xsT_hi, xsT_lo);
    }

    // 2) weight splits
    for (int i = 0; i < 4; i++)
        split_kernel<<<(CC * CC + 255) / 256, 256>>>(W[i], W_hi + (size_t)i * CC * CC,
                                                     W_lo + (size_t)i * CC * CC, CC * CC);

    // 3) Qt[n,o] = xcT . W_c1^T + b_c1[o] ; Kt[n,o] = xsT . W_s1^T + b_s1[o]
    {
        dim3 g(CC / 256, NN / 128, BB);   // (2, 32, 4)
        gemm_mma<2><<<g, 256, GEMM_SMEM>>>(xcT_hi, xcT_lo, W_hi + 0 * CC * CC, W_lo + 0 * CC * CC,
                                           nullptr, qt_hi, qt_lo, b_c1, nullptr,
                                           CC, CC, CC, CC, sNC, 0, sNC);
        gemm_mma<2><<<g, 256, GEMM_SMEM>>>(xsT_hi, xsT_lo, W_hi + 1 * CC * CC, W_lo + 1 * CC * CC,
                                           nullptr, kt_hi, kt_lo, b_s1, nullptr,
                                           CC, CC, CC, CC, sNC, 0, sNC);
    }
    // 4) h[o,n] = W_s2 . xsT^T + b_s2[o]
    {
        dim3 g(NN / 256, CC / 128, BB);   // (16, 4, 4)
        gemm_mma<3><<<g, 256, GEMM_SMEM>>>(W_hi + 2 * CC * CC, W_lo + 2 * CC * CC, xsT_hi, xsT_lo,
                                           nullptr, h_hi, h_lo, b_s2, nullptr,
                                           CC, CC, CC, NN, 0, sNC, sNC);
    }
    // 5) scores[i,j] = Qt . Kt^T (fp32)
    {
        dim3 g(NN / 256, NN / 128, BB);   // (16, 32, 4)
        gemm_mma<0><<<g, 256, GEMM_SMEM>>>(qt_hi, qt_lo, kt_hi, kt_lo,
                                           scores, nullptr, nullptr, nullptr, nullptr,
                                           CC, CC, CC, NN, sNC, sNC, sNN);
    }
    // 6) softmax -> att hi/lo
    softmax_kernel<<<BB * NN, 256>>>(scores, att_hi, att_lo);

    // 7) o2t[i,c] = att . h^T
    {
        dim3 g(CC / 256, NN / 128, BB);   // (2, 32, 4)
        gemm_mma<4><<<g, 256, GEMM_SMEM>>>(att_hi, att_lo, h_hi, h_lo,
                                           nullptr, o2t_hi, o2t_lo, nullptr, nullptr,
                                           NN, NN, NN, CC, sNN, sNC, sNC);
    }
    // 8) out[o,n] = W_csc . o2t^T + b_csc[o] + f_c
    {
        dim3 g(NN / 256, CC / 128, BB);   // (16, 4, 4)
        gemm_mma<1><<<g, 256, GEMM_SMEM>>>(W_hi + 3 * CC * CC, W_lo + 3 * CC * CC, o2t_hi, o2t_lo,
                                           out, nullptr, nullptr, b_csc, f_c,
                                           CC, CC, CC, NN, 0, sNC, sNC);
    }
}